// round 1
// baseline (speedup 1.0000x reference)
#include <cuda_runtime.h>

// Problem constants
#define DIMC   512
#define HEADS  8
#define HD     64
#define NTOK   64
#define BATCH  2048
#define SCALE_Q 0.125f   // 64^-0.5
#define PAD    68        // 64 + 4 : float4-aligned, bank-conflict-free transposed tiles

// Scratch for attention output in [B, N, DIM] layout (256 MB, static device array
// per harness rules: no cudaMalloc anywhere).
__device__ float g_x[(size_t)BATCH * NTOK * DIMC];

// ---------------------------------------------------------------------------
// 64x64x(512) projection tile: acc[4][4] += X(64x512 slice) @ W_rows(64x512)^T
// X tile and W tile are staged transposed in SMEM ([k][row]) so the inner loop
// does two float4 LDS per k. All threads call (contains __syncthreads).
// ---------------------------------------------------------------------------
__device__ __forceinline__ void gemm64_512(const float* __restrict__ X,
                                           const float* __restrict__ W,
                                           float* sXT, float* sWT,
                                           int tid, int tx, int ty,
                                           float acc[4][4]) {
    for (int kc = 0; kc < DIMC; kc += 64) {
        __syncthreads();   // previous consumers of sXT/sWT done
        #pragma unroll
        for (int r = 0; r < 16; r++) {
            int e   = tid + r * 256;
            int row = e >> 6;        // 0..63
            int col = e & 63;        // 0..63 (contiguous in gmem -> coalesced)
            sXT[col * PAD + row] = X[row * DIMC + kc + col];
            sWT[col * PAD + row] = W[row * DIMC + kc + col];
        }
        __syncthreads();
        #pragma unroll 16
        for (int kk = 0; kk < 64; kk++) {
            const float4 a4 = *(const float4*)(sXT + kk * PAD + (ty << 2));
            const float4 b4 = *(const float4*)(sWT + kk * PAD + (tx << 2));
            float a[4] = {a4.x, a4.y, a4.z, a4.w};
            float b[4] = {b4.x, b4.y, b4.z, b4.w};
            #pragma unroll
            for (int i = 0; i < 4; i++)
                #pragma unroll
                for (int j = 0; j < 4; j++)
                    acc[i][j] = fmaf(a[i], b[j], acc[i][j]);
        }
    }
}

// ---------------------------------------------------------------------------
// Kernel 1: one block per (batch, head). Computes Qh, Kh, Vh (64x64 each) from
// the raw inputs + weights, then masked-softmax attention, writes O into
// g_x[b, token, h*64 + d].
// ---------------------------------------------------------------------------
__global__ __launch_bounds__(256, 2)
void attn_fused(const float* __restrict__ q,  const float* __restrict__ k,
                const float* __restrict__ v,  const int*   __restrict__ mask,
                const float* __restrict__ Wq, const float* __restrict__ bq,
                const float* __restrict__ Wk, const float* __restrict__ bk,
                const float* __restrict__ Wv, const float* __restrict__ bv) {
    extern __shared__ float smem[];
    float* sXT = smem;                   // 64*PAD   (working X tile, transposed)
    float* sWT = smem + 1 * 64 * PAD;    // 64*PAD   (working W tile, transposed)
    float* sQT = smem + 2 * 64 * PAD;    // Q^T : [d][token]
    float* sKT = smem + 3 * 64 * PAD;    // K^T : [d][token]
    float* sV  = smem + 4 * 64 * PAD;    // V   : [token][d]
    int*   smask = (int*)(smem + 5 * 64 * PAD);
    float* sST = sXT;                    // scores S^T : [key j][query i] (reuses X/W area)

    const int blk = blockIdx.x;
    const int h   = blk & (HEADS - 1);
    const int b   = blk >> 3;
    const int tid = threadIdx.x;
    const int tx  = tid & 15;            // 16 cols of 4
    const int ty  = tid >> 4;            // 16 rows of 4

    if (tid < NTOK) smask[tid] = mask[b * NTOK + tid];

    // ---- Q projection (scale folded in), stored transposed [d][i] ----
    {
        float acc[4][4] = {};
        gemm64_512(q + (size_t)b * NTOK * DIMC, Wq + (size_t)h * HD * DIMC,
                   sXT, sWT, tid, tx, ty, acc);
        #pragma unroll
        for (int dd = 0; dd < 4; dd++) {
            float bias = bq[h * HD + (tx << 2) + dd];
            #pragma unroll
            for (int ii = 0; ii < 4; ii++)
                sQT[((tx << 2) + dd) * PAD + (ty << 2) + ii] =
                    (acc[ii][dd] + bias) * SCALE_Q;
        }
    }
    // ---- K projection, stored transposed [d][j] ----
    {
        float acc[4][4] = {};
        gemm64_512(k + (size_t)b * NTOK * DIMC, Wk + (size_t)h * HD * DIMC,
                   sXT, sWT, tid, tx, ty, acc);
        #pragma unroll
        for (int dd = 0; dd < 4; dd++) {
            float bias = bk[h * HD + (tx << 2) + dd];
            #pragma unroll
            for (int ii = 0; ii < 4; ii++)
                sKT[((tx << 2) + dd) * PAD + (ty << 2) + ii] = acc[ii][dd] + bias;
        }
    }
    // ---- V projection, stored natural [token j][d] ----
    {
        float acc[4][4] = {};
        gemm64_512(v + (size_t)b * NTOK * DIMC, Wv + (size_t)h * HD * DIMC,
                   sXT, sWT, tid, tx, ty, acc);
        #pragma unroll
        for (int ii = 0; ii < 4; ii++) {
            #pragma unroll
            for (int dd = 0; dd < 4; dd++)
                sV[((ty << 2) + ii) * PAD + (tx << 2) + dd] =
                    acc[ii][dd] + bv[h * HD + (tx << 2) + dd];
        }
    }
    __syncthreads();   // Q/K/V tiles fully materialized; sXT free for reuse

    // ---- S^T[j][i] = sum_d K[j][d] * Qscaled[i][d], with key mask ----
    {
        float acc[4][4] = {};   // acc[jj][ii]
        #pragma unroll 16
        for (int d = 0; d < 64; d++) {
            const float4 k4 = *(const float4*)(sKT + d * PAD + (ty << 2));  // keys
            const float4 q4 = *(const float4*)(sQT + d * PAD + (tx << 2));  // queries
            float kk[4] = {k4.x, k4.y, k4.z, k4.w};
            float qq[4] = {q4.x, q4.y, q4.z, q4.w};
            #pragma unroll
            for (int jj = 0; jj < 4; jj++)
                #pragma unroll
                for (int ii = 0; ii < 4; ii++)
                    acc[jj][ii] = fmaf(kk[jj], qq[ii], acc[jj][ii]);
        }
        #pragma unroll
        for (int jj = 0; jj < 4; jj++) {
            int j = (ty << 2) + jj;
            bool keep = (smask[j] != 0);
            #pragma unroll
            for (int ii = 0; ii < 4; ii++)
                sST[j * PAD + (tx << 2) + ii] = keep ? acc[jj][ii] : -10000.0f;
        }
    }
    __syncthreads();

    // ---- softmax over keys (per query row i). 4 lanes cooperate per row. ----
    {
        int row = tid >> 2;        // query index 0..63
        int p   = tid & 3;         // 16-key slice
        float vreg[16];
        float m = -1e30f;
        #pragma unroll
        for (int s = 0; s < 16; s++) {
            vreg[s] = sST[(p * 16 + s) * PAD + row];
            m = fmaxf(m, vreg[s]);
        }
        m = fmaxf(m, __shfl_xor_sync(0xffffffffu, m, 1));
        m = fmaxf(m, __shfl_xor_sync(0xffffffffu, m, 2));
        float sum = 0.f;
        #pragma unroll
        for (int s = 0; s < 16; s++) {
            vreg[s] = __expf(vreg[s] - m);
            sum += vreg[s];
        }
        sum += __shfl_xor_sync(0xffffffffu, sum, 1);
        sum += __shfl_xor_sync(0xffffffffu, sum, 2);
        float inv = 1.0f / sum;
        #pragma unroll
        for (int s = 0; s < 16; s++)
            sST[(p * 16 + s) * PAD + row] = vreg[s] * inv;
    }
    __syncthreads();

    // ---- O[i][d] = sum_j P^T[j][i] * V[j][d]; write to g_x[b, i, h*64+d] ----
    {
        float acc[4][4] = {};   // acc[ii][dd]
        #pragma unroll 16
        for (int j = 0; j < 64; j++) {
            const float4 p4 = *(const float4*)(sST + j * PAD + (ty << 2));
            const float4 v4 = *(const float4*)(sV  + j * PAD + (tx << 2));
            float pp[4] = {p4.x, p4.y, p4.z, p4.w};
            float vv[4] = {v4.x, v4.y, v4.z, v4.w};
            #pragma unroll
            for (int ii = 0; ii < 4; ii++)
                #pragma unroll
                for (int dd = 0; dd < 4; dd++)
                    acc[ii][dd] = fmaf(pp[ii], vv[dd], acc[ii][dd]);
        }
        #pragma unroll
        for (int ii = 0; ii < 4; ii++) {
            float4 o = make_float4(acc[ii][0], acc[ii][1], acc[ii][2], acc[ii][3]);
            size_t off = ((size_t)b * NTOK + (ty << 2) + ii) * DIMC + h * HD + (tx << 2);
            *(float4*)(g_x + off) = o;
        }
    }
}

// ---------------------------------------------------------------------------
// Kernel 2: out = g_x (131072 x 512) @ Wp^T + bp. 64x64 tiles, same micro-kernel.
// ---------------------------------------------------------------------------
__global__ __launch_bounds__(256, 2)
void proj_out(const float* __restrict__ Wp, const float* __restrict__ bp,
              float* __restrict__ out) {
    __shared__ float sAT[64 * PAD];
    __shared__ float sBT[64 * PAD];

    const int m0  = blockIdx.x * 64;
    const int n0  = blockIdx.y * 64;
    const int tid = threadIdx.x;
    const int tx  = tid & 15;
    const int ty  = tid >> 4;

    float acc[4][4] = {};   // acc[mm][nn]
    for (int kc = 0; kc < DIMC; kc += 64) {
        __syncthreads();
        #pragma unroll
        for (int r = 0; r < 16; r++) {
            int e   = tid + r * 256;
            int row = e >> 6;
            int col = e & 63;
            sAT[col * PAD + row] = g_x[(size_t)(m0 + row) * DIMC + kc + col];
            sBT[col * PAD + row] = Wp[(size_t)(n0 + row) * DIMC + kc + col];
        }
        __syncthreads();
        #pragma unroll 16
        for (int kk = 0; kk < 64; kk++) {
            const float4 a4 = *(const float4*)(sAT + kk * PAD + (ty << 2));
            const float4 b4 = *(const float4*)(sBT + kk * PAD + (tx << 2));
            float a[4] = {a4.x, a4.y, a4.z, a4.w};
            float b[4] = {b4.x, b4.y, b4.z, b4.w};
            #pragma unroll
            for (int i = 0; i < 4; i++)
                #pragma unroll
                for (int j = 0; j < 4; j++)
                    acc[i][j] = fmaf(a[i], b[j], acc[i][j]);
        }
    }
    #pragma unroll
    for (int mm = 0; mm < 4; mm++) {
        float4 o;
        o.x = acc[mm][0] + bp[n0 + (tx << 2) + 0];
        o.y = acc[mm][1] + bp[n0 + (tx << 2) + 1];
        o.z = acc[mm][2] + bp[n0 + (tx << 2) + 2];
        o.w = acc[mm][3] + bp[n0 + (tx << 2) + 3];
        size_t off = (size_t)(m0 + (ty << 2) + mm) * DIMC + n0 + (tx << 2);
        *(float4*)(out + off) = o;
    }
}

extern "C" void kernel_launch(void* const* d_in, const int* in_sizes, int n_in,
                              void* d_out, int out_size) {
    const float* q    = (const float*)d_in[0];
    const float* k    = (const float*)d_in[1];
    const float* v    = (const float*)d_in[2];
    const int*   mask = (const int*)  d_in[3];
    const float* Wq   = (const float*)d_in[4];
    const float* bq   = (const float*)d_in[5];
    const float* Wk   = (const float*)d_in[6];
    const float* bk   = (const float*)d_in[7];
    const float* Wv   = (const float*)d_in[8];
    const float* bv   = (const float*)d_in[9];
    const float* Wp   = (const float*)d_in[10];
    const float* bp   = (const float*)d_in[11];
    float* out = (float*)d_out;

    const int smem1 = (5 * 64 * PAD) * (int)sizeof(float) + NTOK * (int)sizeof(int);
    cudaFuncSetAttribute(attn_fused, cudaFuncAttributeMaxDynamicSharedMemorySize, smem1);

    attn_fused<<<BATCH * HEADS, 256, smem1>>>(q, k, v, mask,
                                              Wq, bq, Wk, bk, Wv, bv);

    dim3 g2((BATCH * NTOK) / 64, DIMC / 64);
    proj_out<<<g2, 256>>>(Wp, bp, out);
}